// round 14
// baseline (speedup 1.0000x reference)
#include <cuda_runtime.h>
#include <cuda_fp16.h>
#include <math.h>
#include <stdint.h>

#define B_ 4
#define S_ 2048
#define D_ 1024
#define H_ 16
#define DH 64

__device__ __half g_qh[B_*S_*H_*DH];     // fp16 q (post-rope, scaled)
__device__ __half g_kh[B_*S_*H_*DH];     // fp16 k (post-rope)
__device__ __half g_vh[B_*S_*H_*DH];     // fp16 v
__device__ __half g_xh[B_*S_*H_*DH];     // flash out (A of out-proj)
__device__ __half g_ah[B_*S_*D_];        // fp16 inputs
__device__ __half g_wth[4*1024*1024];    // transposed fp16 weights
__device__ float2 g_tab[S_*32];          // rope (sin,cos) table

__device__ __forceinline__ uint32_t smem_u32(const void* p) {
    uint32_t a;
    asm("{ .reg .u64 t; cvta.to.shared.u64 t, %1; cvt.u32.u64 %0, t; }" : "=r"(a) : "l"(p));
    return a;
}

#define MMA_F16(c0,c1,c2,c3,a0,a1,a2,a3,b0,b1)                           \
    asm volatile(                                                        \
        "mma.sync.aligned.m16n8k16.row.col.f32.f16.f16.f32 "             \
        "{%0,%1,%2,%3}, {%4,%5,%6,%7}, {%8,%9}, {%0,%1,%2,%3};"          \
        : "+f"(c0), "+f"(c1), "+f"(c2), "+f"(c3)                         \
        : "r"(a0), "r"(a1), "r"(a2), "r"(a3), "r"(b0), "r"(b1))

#define LDSM4(r0,r1,r2,r3,a)                                             \
    asm volatile("ldmatrix.sync.aligned.m8n8.x4.shared.b16 "             \
        "{%0,%1,%2,%3}, [%4];"                                           \
        : "=r"(r0), "=r"(r1), "=r"(r2), "=r"(r3) : "r"(a))

#define LDSM4T(r0,r1,r2,r3,a)                                            \
    asm volatile("ldmatrix.sync.aligned.m8n8.x4.trans.shared.b16 "       \
        "{%0,%1,%2,%3}, [%4];"                                           \
        : "=r"(r0), "=r"(r1), "=r"(r2), "=r"(r3) : "r"(a))

#define CP16(dst, src) asm volatile("cp.async.cg.shared.global [%0], [%1], 16;" :: "r"(dst), "l"(src))
#define CP_COMMIT()    asm volatile("cp.async.commit_group;" ::: "memory")
#define CP_WAIT0()     asm volatile("cp.async.wait_group 0;" ::: "memory")

// ---------------------------------------------------------------------------
__global__ __launch_bounds__(256) void build_tab()
{
    const int idx = blockIdx.x * 256 + threadIdx.x;
    const int s = idx >> 5;
    const int d = idx & 31;
    const float ang = (float)s * expf(-(float)d * 0.28782313662425574f);
    float sv, cv;
    sincosf(ang, &sv, &cv);
    g_tab[idx] = make_float2(sv, cv);
}

__global__ __launch_bounds__(256) void to_half(
    const float* __restrict__ src, __half* __restrict__ dst)
{
    const size_t i = (size_t)(blockIdx.x * blockDim.x + threadIdx.x) * 8;
    float4 v0 = *(const float4*)(src + i);
    float4 v1 = *(const float4*)(src + i + 4);
    __half2 h[4];
    h[0] = __floats2half2_rn(v0.x, v0.y);
    h[1] = __floats2half2_rn(v0.z, v0.w);
    h[2] = __floats2half2_rn(v1.x, v1.y);
    h[3] = __floats2half2_rn(v1.z, v1.w);
    *(uint4*)(dst + i) = *(uint4*)h;
}

__global__ __launch_bounds__(256) void transpose_half(
    const float* __restrict__ w0, const float* __restrict__ w1,
    const float* __restrict__ w2, const float* __restrict__ w3,
    __half* __restrict__ dst)
{
    __shared__ float tile[32][33];
    const int z = blockIdx.z;
    const float* src = (z == 0) ? w0 : (z == 1) ? w1 : (z == 2) ? w2 : w3;
    __half* out = dst + (size_t)z * 1024 * 1024;
    const int n0 = blockIdx.x * 32;
    const int k0 = blockIdx.y * 32;
    const int tx = threadIdx.x;
    const int ty = threadIdx.y;

    #pragma unroll
    for (int j = 0; j < 4; j++)
        tile[ty + j * 8][tx] = src[(size_t)(k0 + ty + j * 8) * 1024 + n0 + tx];
    __syncthreads();
    #pragma unroll
    for (int j = 0; j < 4; j++)
        out[(size_t)(n0 + ty + j * 8) * 1024 + k0 + tx] = __float2half(tile[tx][ty + j * 8]);
}

// ---------------------------------------------------------------------------
// fp16 mma GEMM: BK=32 per stage, 4 stages = 2 pairs, one barrier per PAIR
// (2 stages = 64 mma/warp between barriers). ldmatrix fragment loads.
// ---------------------------------------------------------------------------
#define GSTR 20
#define STG_WORDS (128 * GSTR)
#define GSMEM_BYTES (8 * STG_WORDS * 4)        // 80 KB

__global__ __launch_bounds__(256) void gemm_h(
    const __half* __restrict__ A, const __half* __restrict__ Bt,
    float* __restrict__ Cf, __half* __restrict__ qh, __half* __restrict__ kh,
    __half* __restrict__ vh, const int* __restrict__ segpos, int fused)
{
    extern __shared__ uint32_t smw[];
    const uint32_t sbase = smem_u32(smw);

    const int tid  = threadIdx.x;
    const int warp = tid >> 5;
    const int lane = tid & 31;
    const int g = lane >> 2;
    const int t = lane & 3;
    const int wm = warp >> 1;
    const int wn = warp & 1;

    const int m0 = blockIdx.y * 128;
    const int n0 = blockIdx.x * 128;
    const int sel  = n0 >> 10;
    const int col0 = n0 & 1023;

    const int lrow = tid >> 1;
    const int hh   = (tid & 1) * 16;
    const __half* ag = A  + (size_t)(m0 + lrow) * 1024 + hh;
    const __half* bg = Bt + (size_t)(n0 + lrow) * 1024 + hh;
    const uint32_t adst = sbase + (uint32_t)(lrow * 80 + hh * 2);
    const uint32_t bdst = adst + 4 * STG_WORDS * 4;

    uint32_t aoff[2], boff[4];
    #pragma unroll
    for (int mt = 0; mt < 2; mt++)
        aoff[mt] = (uint32_t)(((wm * 32 + mt * 16 + (lane & 15)) * 20
                               + ((lane & 16) ? 4 : 0)) * 4);
    #pragma unroll
    for (int j = 0; j < 4; j++)
        boff[j] = (uint32_t)(((wn * 64 + j * 16 + (lane & 7) + ((lane & 16) ? 8 : 0)) * 20
                              + ((lane & 8) ? 4 : 0)) * 4);

    float c[2][8][4];
    #pragma unroll
    for (int mt = 0; mt < 2; mt++)
        #pragma unroll
        for (int nt = 0; nt < 8; nt++)
            #pragma unroll
            for (int r = 0; r < 4; r++) c[mt][nt][r] = 0.f;

    // prologue: pair 0 (stages 0,1 = k-tiles 0,1)
    #pragma unroll
    for (int st = 0; st < 2; st++) {
        CP16(adst + st * 10240,      ag + st * 32);
        CP16(adst + st * 10240 + 16, ag + st * 32 + 8);
        CP16(bdst + st * 10240,      bg + st * 32);
        CP16(bdst + st * 10240 + 16, bg + st * 32 + 8);
    }
    CP_COMMIT();

    for (int ip = 0; ip < 16; ip++) {
        CP_WAIT0();
        __syncthreads();

        if (ip + 1 < 16) {
            const int ps = ((ip + 1) & 1) * 2;   // pair slot (stages ps, ps+1)
            #pragma unroll
            for (int st = 0; st < 2; st++) {
                const int ktile = 2 * (ip + 1) + st;
                CP16(adst + (ps + st) * 10240,      ag + ktile * 32);
                CP16(adst + (ps + st) * 10240 + 16, ag + ktile * 32 + 8);
                CP16(bdst + (ps + st) * 10240,      bg + ktile * 32);
                CP16(bdst + (ps + st) * 10240 + 16, bg + ktile * 32 + 8);
            }
            CP_COMMIT();
        }

        const int cps = (ip & 1) * 2;
        #pragma unroll
        for (int st = 0; st < 2; st++) {
            const uint32_t abuf = sbase + (uint32_t)((cps + st) * 10240);
            const uint32_t bbuf = abuf + 4 * STG_WORDS * 4;
            #pragma unroll
            for (int ks = 0; ks < 2; ks++) {
                const uint32_t kbyte = ks * 32;
                uint32_t afr[2][4];
                #pragma unroll
                for (int mt = 0; mt < 2; mt++)
                    LDSM4(afr[mt][0], afr[mt][1], afr[mt][2], afr[mt][3],
                          abuf + aoff[mt] + kbyte);
                uint32_t bfr[8][2];
                #pragma unroll
                for (int j = 0; j < 4; j++)
                    LDSM4(bfr[2*j][0], bfr[2*j][1], bfr[2*j+1][0], bfr[2*j+1][1],
                          bbuf + boff[j] + kbyte);
                #pragma unroll
                for (int mt = 0; mt < 2; mt++)
                    #pragma unroll
                    for (int nt = 0; nt < 8; nt++)
                        MMA_F16(c[mt][nt][0], c[mt][nt][1], c[mt][nt][2], c[mt][nt][3],
                                afr[mt][0], afr[mt][1], afr[mt][2], afr[mt][3],
                                bfr[nt][0], bfr[nt][1]);
            }
        }
    }

    if (!fused) {
        #pragma unroll
        for (int mt = 0; mt < 2; mt++) {
            const int r = m0 + wm * 32 + mt * 16 + g;
            #pragma unroll
            for (int nt = 0; nt < 8; nt++) {
                const int cc = col0 + wn * 64 + nt * 8 + t * 2;
                *(float2*)(Cf + (size_t)r * 1024 + cc)       = make_float2(c[mt][nt][0], c[mt][nt][1]);
                *(float2*)(Cf + (size_t)(r + 8) * 1024 + cc) = make_float2(c[mt][nt][2], c[mt][nt][3]);
            }
        }
    } else if (sel == 2) {
        #pragma unroll
        for (int mt = 0; mt < 2; mt++) {
            const int r = m0 + wm * 32 + mt * 16 + g;
            #pragma unroll
            for (int nt = 0; nt < 8; nt++) {
                const int cc = col0 + wn * 64 + nt * 8 + t * 2;
                *(__half2*)(vh + (size_t)r * 1024 + cc) =
                    __floats2half2_rn(c[mt][nt][0], c[mt][nt][1]);
                *(__half2*)(vh + (size_t)(r + 8) * 1024 + cc) =
                    __floats2half2_rn(c[mt][nt][2], c[mt][nt][3]);
            }
        }
    } else {
        __half* dst = (sel == 0) ? qh : kh;
        const float scl = (sel == 0) ? 0.125f : 1.0f;
        #pragma unroll
        for (int mt = 0; mt < 2; mt++) {
            const int r = m0 + wm * 32 + mt * 16 + g;
            const int p0 = segpos[r];
            const int p1 = segpos[r + 8];
            #pragma unroll
            for (int nt = 0; nt < 4; nt++) {
                const int d = nt * 8 + t * 2;
                float4 t0 = *(const float4*)(&g_tab[p0 * 32 + d]);
                float4 t1 = *(const float4*)(&g_tab[p1 * 32 + d]);
                const int cc = col0 + wn * 64 + nt * 8 + t * 2;
                float f0 = (c[mt][nt][0] * t0.y - c[mt][nt+4][0] * t0.x) * scl;
                float s0 = (c[mt][nt+4][0] * t0.y + c[mt][nt][0] * t0.x) * scl;
                float f1 = (c[mt][nt][1] * t0.w - c[mt][nt+4][1] * t0.z) * scl;
                float s1 = (c[mt][nt+4][1] * t0.w + c[mt][nt][1] * t0.z) * scl;
                *(__half2*)(dst + (size_t)r * 1024 + cc)      = __floats2half2_rn(f0, f1);
                *(__half2*)(dst + (size_t)r * 1024 + cc + 32) = __floats2half2_rn(s0, s1);
                f0 = (c[mt][nt][2] * t1.y - c[mt][nt+4][2] * t1.x) * scl;
                s0 = (c[mt][nt+4][2] * t1.y + c[mt][nt][2] * t1.x) * scl;
                f1 = (c[mt][nt][3] * t1.w - c[mt][nt+4][3] * t1.z) * scl;
                s1 = (c[mt][nt+4][3] * t1.w + c[mt][nt][3] * t1.z) * scl;
                *(__half2*)(dst + (size_t)(r + 8) * 1024 + cc)      = __floats2half2_rn(f0, f1);
                *(__half2*)(dst + (size_t)(r + 8) * 1024 + cc + 32) = __floats2half2_rn(s0, s1);
            }
        }
    }
}

// ---------------------------------------------------------------------------
// fp16-mma flash attention (unchanged from R13): cp.async K/V, ldmatrix frags.
// ---------------------------------------------------------------------------
#define BQ 128
#define QSTR 36
#define PSTR2 36
#define QBYTES (128 * QSTR * 4)
#define KVSTRB 144
#define KVB (64 * KVSTRB)
#define PBYTES (8 * 16 * PSTR2 * 4)
#define FH_SMEM_BYTES (QBYTES + 4 * KVB + PBYTES)   // 73728

__global__ __launch_bounds__(256) void flash_h()
{
    extern __shared__ char smc[];
    const uint32_t sb = smem_u32(smc);
    uint32_t* Qs = (uint32_t*)smc;
    uint32_t* Pw = (uint32_t*)(smc + QBYTES + 4 * KVB);

    const int qt = (int)gridDim.x - 1 - (int)blockIdx.x;
    const int h  = blockIdx.y;
    const int b  = blockIdx.z;
    const int tid  = threadIdx.x;
    const int warp = tid >> 5;
    const int lane = tid & 31;
    const int g = lane >> 2;
    const int t = lane & 3;
    const int q0 = qt * BQ;
    const int wrow0 = warp * 16;
    uint32_t* Ps = Pw + warp * 16 * PSTR2;

    {
        const int qr = tid >> 1;
        const int hc = (tid & 1) * 16;
        const __half* qg = g_qh + (((size_t)(b * S_ + q0 + qr)) * H_ + h) * DH + hc * 2;
        uint4 u0 = *(const uint4*)(qg);
        uint4 u1 = *(const uint4*)(qg + 8);
        uint4 u2 = *(const uint4*)(qg + 16);
        uint4 u3 = *(const uint4*)(qg + 24);
        *(uint4*)&Qs[qr * QSTR + hc]      = u0;
        *(uint4*)&Qs[qr * QSTR + hc + 4]  = u1;
        *(uint4*)&Qs[qr * QSTR + hc + 8]  = u2;
        *(uint4*)&Qs[qr * QSTR + hc + 12] = u3;
    }

    const int srow = tid >> 2;
    const int scp  = tid & 3;

    const uint32_t koffs = (uint32_t)(((lane & 7) + ((lane & 16) ? 8 : 0)) * KVSTRB
                                      + ((lane & 8) ? 16 : 0));
    const uint32_t voffs = (uint32_t)(((lane & 7) + ((lane & 8) ? 8 : 0)) * KVSTRB
                                      + ((lane & 16) ? 16 : 0));

    float o[8][4];
    #pragma unroll
    for (int nt = 0; nt < 8; nt++)
        #pragma unroll
        for (int r = 0; r < 4; r++) o[nt][r] = 0.f;
    float m0r = -INFINITY, m1r = -INFINITY, l0 = 0.f, l1 = 0.f;

    const int nkt = 2 * qt + 2;

    {
        const size_t goff = (((size_t)(b * S_ + srow)) * H_ + h) * DH + scp * 16;
        const uint32_t kd = sb + QBYTES + (uint32_t)(srow * KVSTRB + scp * 32);
        const uint32_t vd = kd + KVB;
        CP16(kd,      g_kh + goff);
        CP16(kd + 16, g_kh + goff + 8);
        CP16(vd,      g_vh + goff);
        CP16(vd + 16, g_vh + goff + 8);
        CP_COMMIT();
    }

    for (int kt = 0; kt < nkt; kt++) {
        const int k0 = kt * 64;
        const int buf = kt & 1;
        const uint32_t kbase = sb + QBYTES + (uint32_t)(buf * 2 * KVB);
        const uint32_t vbase = kbase + KVB;

        CP_WAIT0();
        __syncthreads();

        if (kt + 1 < nkt) {
            const int kn = (kt + 1) * 64;
            const size_t goff = (((size_t)(b * S_ + kn + srow)) * H_ + h) * DH + scp * 16;
            const uint32_t kd = sb + QBYTES + (uint32_t)((buf ^ 1) * 2 * KVB
                                 + srow * KVSTRB + scp * 32);
            const uint32_t vd = kd + KVB;
            CP16(kd,      g_kh + goff);
            CP16(kd + 16, g_kh + goff + 8);
            CP16(vd,      g_vh + goff);
            CP16(vd + 16, g_vh + goff + 8);
            CP_COMMIT();
        }

        float s[8][4];
        #pragma unroll
        for (int nt = 0; nt < 8; nt++)
            #pragma unroll
            for (int r = 0; r < 4; r++) s[nt][r] = 0.f;

        #pragma unroll
        for (int ks = 0; ks < 4; ks++) {
            const int kb = ks * 8;
            uint32_t a0 = Qs[(wrow0 + g) * QSTR + kb + t];
            uint32_t a1 = Qs[(wrow0 + g + 8) * QSTR + kb + t];
            uint32_t a2 = Qs[(wrow0 + g) * QSTR + kb + t + 4];
            uint32_t a3 = Qs[(wrow0 + g + 8) * QSTR + kb + t + 4];
            #pragma unroll
            for (int ntp = 0; ntp < 4; ntp++) {
                uint32_t b00, b01, b10, b11;
                LDSM4(b00, b01, b10, b11,
                      kbase + koffs + (uint32_t)(ntp * 16 * KVSTRB + ks * 32));
                MMA_F16(s[2*ntp][0],   s[2*ntp][1],   s[2*ntp][2],   s[2*ntp][3],
                        a0, a1, a2, a3, b00, b01);
                MMA_F16(s[2*ntp+1][0], s[2*ntp+1][1], s[2*ntp+1][2], s[2*ntp+1][3],
                        a0, a1, a2, a3, b10, b11);
            }
        }

        if (kt >= 2 * qt) {
            const int row0 = q0 + wrow0 + g;
            #pragma unroll
            for (int nt = 0; nt < 8; nt++) {
                const int col = k0 + nt * 8 + 2 * t;
                if (col     > row0)     s[nt][0] = -INFINITY;
                if (col + 1 > row0)     s[nt][1] = -INFINITY;
                if (col     > row0 + 8) s[nt][2] = -INFINITY;
                if (col + 1 > row0 + 8) s[nt][3] = -INFINITY;
            }
        }

        float mx0 = -INFINITY, mx1 = -INFINITY;
        #pragma unroll
        for (int nt = 0; nt < 8; nt++) {
            mx0 = fmaxf(mx0, fmaxf(s[nt][0], s[nt][1]));
            mx1 = fmaxf(mx1, fmaxf(s[nt][2], s[nt][3]));
        }
        mx0 = fmaxf(mx0, __shfl_xor_sync(0xffffffffu, mx0, 1));
        mx0 = fmaxf(mx0, __shfl_xor_sync(0xffffffffu, mx0, 2));
        mx1 = fmaxf(mx1, __shfl_xor_sync(0xffffffffu, mx1, 1));
        mx1 = fmaxf(mx1, __shfl_xor_sync(0xffffffffu, mx1, 2));

        const float mn0 = fmaxf(m0r, mx0);
        const float mn1 = fmaxf(m1r, mx1);
        const float sc0 = __expf(m0r - mn0);
        const float sc1 = __expf(m1r - mn1);

        float ls0 = 0.f, ls1 = 0.f;
        #pragma unroll
        for (int nt = 0; nt < 8; nt++) {
            float p0 = __expf(s[nt][0] - mn0);
            float p1 = __expf(s[nt][1] - mn0);
            float p2 = __expf(s[nt][2] - mn1);
            float p3 = __expf(s[nt][3] - mn1);
            ls0 += p0 + p1;
            ls1 += p2 + p3;
            __half2 h01 = __floats2half2_rn(p0, p1);
            __half2 h23 = __floats2half2_rn(p2, p3);
            Ps[g * PSTR2 + nt * 4 + t]       = *(uint32_t*)&h01;
            Ps[(g + 8) * PSTR2 + nt * 4 + t] = *(uint32_t*)&h23;
        }
        ls0 += __shfl_xor_sync(0xffffffffu, ls0, 1);
        ls0 += __shfl_xor_sync(0xffffffffu, ls0, 2);
        ls1 += __shfl_xor_sync(0xffffffffu, ls1, 1);
        ls1 += __shfl_xor_sync(0xffffffffu, ls1, 2);
        l0 = l0 * sc0 + ls0;
        l1 = l1 * sc1 + ls1;
        #pragma unroll
        for (int nt = 0; nt < 8; nt++) {
            o[nt][0] *= sc0; o[nt][1] *= sc0;
            o[nt][2] *= sc1; o[nt][3] *= sc1;
        }
        m0r = mn0; m1r = mn1;

        __syncwarp();

        #pragma unroll
        for (int ks = 0; ks < 4; ks++) {
            const int kb = ks * 8;
            uint32_t a0 = Ps[g * PSTR2 + kb + t];
            uint32_t a1 = Ps[(g + 8) * PSTR2 + kb + t];
            uint32_t a2 = Ps[g * PSTR2 + kb + t + 4];
            uint32_t a3 = Ps[(g + 8) * PSTR2 + kb + t + 4];
            #pragma unroll
            for (int ntp = 0; ntp < 4; ntp++) {
                uint32_t b00, b01, b10, b11;
                LDSM4T(b00, b01, b10, b11,
                       vbase + voffs + (uint32_t)(ks * 16 * KVSTRB + ntp * 32));
                MMA_F16(o[2*ntp][0],   o[2*ntp][1],   o[2*ntp][2],   o[2*ntp][3],
                        a0, a1, a2, a3, b00, b01);
                MMA_F16(o[2*ntp+1][0], o[2*ntp+1][1], o[2*ntp+1][2], o[2*ntp+1][3],
                        a0, a1, a2, a3, b10, b11);
            }
        }
        __syncwarp();
    }

    const float i0 = 1.f / l0;
    const float i1 = 1.f / l1;
    __half* xg0 = g_xh + (((size_t)(b * S_ + q0 + wrow0 + g)) * H_ + h) * DH;
    __half* xg1 = xg0 + (size_t)8 * H_ * DH;
    #pragma unroll
    for (int nt = 0; nt < 8; nt++) {
        *(__half2*)(xg0 + nt * 8 + 2 * t) = __floats2half2_rn(o[nt][0] * i0, o[nt][1] * i0);
        *(__half2*)(xg1 + nt * 8 + 2 * t) = __floats2half2_rn(o[nt][2] * i1, o[nt][3] * i1);
    }
}

// ---------------------------------------------------------------------------
extern "C" void kernel_launch(void* const* d_in, const int* in_sizes, int n_in,
                              void* d_out, int out_size)
{
    (void)in_sizes; (void)n_in; (void)out_size;
    const float* inputs = (const float*)d_in[0];
    const float* w_q    = (const float*)d_in[1];
    const float* w_k    = (const float*)d_in[2];
    const float* w_v    = (const float*)d_in[3];
    const float* w_out  = (const float*)d_in[4];
    const int*   segpos = (const int*)d_in[5];
    float* out = (float*)d_out;

    __half *qh, *kh, *vh, *xh, *ah, *wth;
    cudaGetSymbolAddress((void**)&qh, g_qh);
    cudaGetSymbolAddress((void**)&kh, g_kh);
    cudaGetSymbolAddress((void**)&vh, g_vh);
    cudaGetSymbolAddress((void**)&xh, g_xh);
    cudaGetSymbolAddress((void**)&ah, g_ah);
    cudaGetSymbolAddress((void**)&wth, g_wth);

    build_tab<<<S_ * 32 / 256, 256>>>();
    to_half<<<B_ * S_ * D_ / (256 * 8), 256>>>(inputs, ah);
    transpose_half<<<dim3(32, 32, 4), dim3(32, 8)>>>(w_q, w_k, w_v, w_out, wth);

    cudaFuncSetAttribute(gemm_h, cudaFuncAttributeMaxDynamicSharedMemorySize, GSMEM_BYTES);
    gemm_h<<<dim3(24, 64), 256, GSMEM_BYTES>>>(ah, wth, nullptr, qh, kh, vh, segpos, 1);

    cudaFuncSetAttribute(flash_h, cudaFuncAttributeMaxDynamicSharedMemorySize, FH_SMEM_BYTES);
    flash_h<<<dim3(S_ / BQ, H_, B_), 256, FH_SMEM_BYTES>>>();

    gemm_h<<<dim3(8, 64), 256, GSMEM_BYTES>>>(xh, wth + (size_t)3 * 1024 * 1024,
                                              out, nullptr, nullptr, nullptr, nullptr, 0);
}

// round 15
// speedup vs baseline: 1.1032x; 1.1032x over previous
#include <cuda_runtime.h>
#include <cuda_fp16.h>
#include <math.h>
#include <stdint.h>

#define B_ 4
#define S_ 2048
#define D_ 1024
#define H_ 16
#define DH 64

__device__ __half g_qh[B_*S_*H_*DH];     // fp16 q (post-rope, scaled)
__device__ __half g_kh[B_*S_*H_*DH];     // fp16 k (post-rope)
__device__ __half g_vh[B_*S_*H_*DH];     // fp16 v
__device__ __half g_xh[B_*S_*H_*DH];     // flash out (A of out-proj)
__device__ __half g_ah[B_*S_*D_];        // fp16 inputs
__device__ __half g_wth[4*1024*1024];    // transposed fp16 weights
__device__ float2 g_tab[S_*32];          // rope (sin,cos) table

__device__ __forceinline__ uint32_t smem_u32(const void* p) {
    uint32_t a;
    asm("{ .reg .u64 t; cvta.to.shared.u64 t, %1; cvt.u32.u64 %0, t; }" : "=r"(a) : "l"(p));
    return a;
}

#define MMA_F16(c0,c1,c2,c3,a0,a1,a2,a3,b0,b1)                           \
    asm volatile(                                                        \
        "mma.sync.aligned.m16n8k16.row.col.f32.f16.f16.f32 "             \
        "{%0,%1,%2,%3}, {%4,%5,%6,%7}, {%8,%9}, {%0,%1,%2,%3};"          \
        : "+f"(c0), "+f"(c1), "+f"(c2), "+f"(c3)                         \
        : "r"(a0), "r"(a1), "r"(a2), "r"(a3), "r"(b0), "r"(b1))

#define LDSM4(r0,r1,r2,r3,a)                                             \
    asm volatile("ldmatrix.sync.aligned.m8n8.x4.shared.b16 "             \
        "{%0,%1,%2,%3}, [%4];"                                           \
        : "=r"(r0), "=r"(r1), "=r"(r2), "=r"(r3) : "r"(a))

#define LDSM4T(r0,r1,r2,r3,a)                                            \
    asm volatile("ldmatrix.sync.aligned.m8n8.x4.trans.shared.b16 "       \
        "{%0,%1,%2,%3}, [%4];"                                           \
        : "=r"(r0), "=r"(r1), "=r"(r2), "=r"(r3) : "r"(a))

#define CP16(dst, src) asm volatile("cp.async.cg.shared.global [%0], [%1], 16;" :: "r"(dst), "l"(src))
#define CP_COMMIT()    asm volatile("cp.async.commit_group;" ::: "memory")
#define CP_WAIT0()     asm volatile("cp.async.wait_group 0;" ::: "memory")

// ---------------------------------------------------------------------------
__global__ __launch_bounds__(256) void build_tab()
{
    const int idx = blockIdx.x * 256 + threadIdx.x;
    const int s = idx >> 5;
    const int d = idx & 31;
    const float ang = (float)s * expf(-(float)d * 0.28782313662425574f);
    float sv, cv;
    sincosf(ang, &sv, &cv);
    g_tab[idx] = make_float2(sv, cv);
}

__global__ __launch_bounds__(256) void to_half(
    const float* __restrict__ src, __half* __restrict__ dst)
{
    const size_t i = (size_t)(blockIdx.x * blockDim.x + threadIdx.x) * 8;
    float4 v0 = *(const float4*)(src + i);
    float4 v1 = *(const float4*)(src + i + 4);
    __half2 h[4];
    h[0] = __floats2half2_rn(v0.x, v0.y);
    h[1] = __floats2half2_rn(v0.z, v0.w);
    h[2] = __floats2half2_rn(v1.x, v1.y);
    h[3] = __floats2half2_rn(v1.z, v1.w);
    *(uint4*)(dst + i) = *(uint4*)h;
}

__global__ __launch_bounds__(256) void transpose_half(
    const float* __restrict__ w0, const float* __restrict__ w1,
    const float* __restrict__ w2, const float* __restrict__ w3,
    __half* __restrict__ dst)
{
    __shared__ float tile[32][33];
    const int z = blockIdx.z;
    const float* src = (z == 0) ? w0 : (z == 1) ? w1 : (z == 2) ? w2 : w3;
    __half* out = dst + (size_t)z * 1024 * 1024;
    const int n0 = blockIdx.x * 32;
    const int k0 = blockIdx.y * 32;
    const int tx = threadIdx.x;
    const int ty = threadIdx.y;

    #pragma unroll
    for (int j = 0; j < 4; j++)
        tile[ty + j * 8][tx] = src[(size_t)(k0 + ty + j * 8) * 1024 + n0 + tx];
    __syncthreads();
    #pragma unroll
    for (int j = 0; j < 4; j++)
        out[(size_t)(n0 + ty + j * 8) * 1024 + k0 + tx] = __float2half(tile[tx][ty + j * 8]);
}

// ---------------------------------------------------------------------------
// fp16 mma GEMM: BK=32 per stage, 4 stages = 2 pairs, one barrier per PAIR
// (64 mma/warp between barriers). __launch_bounds__(256,2) pins regs <= 128
// so 2 CTAs/SM co-reside (R14 regression root cause: 130 regs -> 1 CTA).
// ---------------------------------------------------------------------------
#define GSTR 20
#define STG_WORDS (128 * GSTR)
#define GSMEM_BYTES (8 * STG_WORDS * 4)        // 80 KB

__global__ __launch_bounds__(256, 2) void gemm_h(
    const __half* __restrict__ A, const __half* __restrict__ Bt,
    float* __restrict__ Cf, __half* __restrict__ qh, __half* __restrict__ kh,
    __half* __restrict__ vh, const int* __restrict__ segpos, int fused)
{
    extern __shared__ uint32_t smw[];
    const uint32_t sbase = smem_u32(smw);

    const int tid  = threadIdx.x;
    const int warp = tid >> 5;
    const int lane = tid & 31;
    const int g = lane >> 2;
    const int t = lane & 3;
    const int wm = warp >> 1;
    const int wn = warp & 1;

    const int m0 = blockIdx.y * 128;
    const int n0 = blockIdx.x * 128;
    const int sel  = n0 >> 10;
    const int col0 = n0 & 1023;

    const int lrow = tid >> 1;
    const int hh   = (tid & 1) * 16;
    const __half* ag = A  + (size_t)(m0 + lrow) * 1024 + hh;
    const __half* bg = Bt + (size_t)(n0 + lrow) * 1024 + hh;
    const uint32_t adst = sbase + (uint32_t)(lrow * 80 + hh * 2);
    const uint32_t bdst = adst + 4 * STG_WORDS * 4;

    uint32_t aoff[2], boff[4];
    #pragma unroll
    for (int mt = 0; mt < 2; mt++)
        aoff[mt] = (uint32_t)(((wm * 32 + mt * 16 + (lane & 15)) * 20
                               + ((lane & 16) ? 4 : 0)) * 4);
    #pragma unroll
    for (int j = 0; j < 4; j++)
        boff[j] = (uint32_t)(((wn * 64 + j * 16 + (lane & 7) + ((lane & 16) ? 8 : 0)) * 20
                              + ((lane & 8) ? 4 : 0)) * 4);

    float c[2][8][4];
    #pragma unroll
    for (int mt = 0; mt < 2; mt++)
        #pragma unroll
        for (int nt = 0; nt < 8; nt++)
            #pragma unroll
            for (int r = 0; r < 4; r++) c[mt][nt][r] = 0.f;

    // prologue: pair 0 (stages 0,1 = k-tiles 0,1)
    #pragma unroll
    for (int st = 0; st < 2; st++) {
        CP16(adst + st * 10240,      ag + st * 32);
        CP16(adst + st * 10240 + 16, ag + st * 32 + 8);
        CP16(bdst + st * 10240,      bg + st * 32);
        CP16(bdst + st * 10240 + 16, bg + st * 32 + 8);
    }
    CP_COMMIT();

    for (int ip = 0; ip < 16; ip++) {
        CP_WAIT0();
        __syncthreads();

        if (ip + 1 < 16) {
            const int ps = ((ip + 1) & 1) * 2;
            #pragma unroll
            for (int st = 0; st < 2; st++) {
                const int ktile = 2 * (ip + 1) + st;
                CP16(adst + (ps + st) * 10240,      ag + ktile * 32);
                CP16(adst + (ps + st) * 10240 + 16, ag + ktile * 32 + 8);
                CP16(bdst + (ps + st) * 10240,      bg + ktile * 32);
                CP16(bdst + (ps + st) * 10240 + 16, bg + ktile * 32 + 8);
            }
            CP_COMMIT();
        }

        const int cps = (ip & 1) * 2;
        #pragma unroll
        for (int st = 0; st < 2; st++) {
            const uint32_t abuf = sbase + (uint32_t)((cps + st) * 10240);
            const uint32_t bbuf = abuf + 4 * STG_WORDS * 4;
            #pragma unroll
            for (int ks = 0; ks < 2; ks++) {
                const uint32_t kbyte = ks * 32;
                uint32_t afr[2][4];
                #pragma unroll
                for (int mt = 0; mt < 2; mt++)
                    LDSM4(afr[mt][0], afr[mt][1], afr[mt][2], afr[mt][3],
                          abuf + aoff[mt] + kbyte);
                uint32_t bfr[8][2];
                #pragma unroll
                for (int j = 0; j < 4; j++)
                    LDSM4(bfr[2*j][0], bfr[2*j][1], bfr[2*j+1][0], bfr[2*j+1][1],
                          bbuf + boff[j] + kbyte);
                #pragma unroll
                for (int mt = 0; mt < 2; mt++)
                    #pragma unroll
                    for (int nt = 0; nt < 8; nt++)
                        MMA_F16(c[mt][nt][0], c[mt][nt][1], c[mt][nt][2], c[mt][nt][3],
                                afr[mt][0], afr[mt][1], afr[mt][2], afr[mt][3],
                                bfr[nt][0], bfr[nt][1]);
            }
        }
    }

    if (!fused) {
        #pragma unroll
        for (int mt = 0; mt < 2; mt++) {
            const int r = m0 + wm * 32 + mt * 16 + g;
            #pragma unroll
            for (int nt = 0; nt < 8; nt++) {
                const int cc = col0 + wn * 64 + nt * 8 + t * 2;
                *(float2*)(Cf + (size_t)r * 1024 + cc)       = make_float2(c[mt][nt][0], c[mt][nt][1]);
                *(float2*)(Cf + (size_t)(r + 8) * 1024 + cc) = make_float2(c[mt][nt][2], c[mt][nt][3]);
            }
        }
    } else if (sel == 2) {
        #pragma unroll
        for (int mt = 0; mt < 2; mt++) {
            const int r = m0 + wm * 32 + mt * 16 + g;
            #pragma unroll
            for (int nt = 0; nt < 8; nt++) {
                const int cc = col0 + wn * 64 + nt * 8 + t * 2;
                *(__half2*)(vh + (size_t)r * 1024 + cc) =
                    __floats2half2_rn(c[mt][nt][0], c[mt][nt][1]);
                *(__half2*)(vh + (size_t)(r + 8) * 1024 + cc) =
                    __floats2half2_rn(c[mt][nt][2], c[mt][nt][3]);
            }
        }
    } else {
        __half* dst = (sel == 0) ? qh : kh;
        const float scl = (sel == 0) ? 0.125f : 1.0f;
        #pragma unroll
        for (int mt = 0; mt < 2; mt++) {
            const int r = m0 + wm * 32 + mt * 16 + g;
            const int p0 = segpos[r];
            const int p1 = segpos[r + 8];
            #pragma unroll
            for (int nt = 0; nt < 4; nt++) {
                const int d = nt * 8 + t * 2;
                float4 t0 = *(const float4*)(&g_tab[p0 * 32 + d]);
                float4 t1 = *(const float4*)(&g_tab[p1 * 32 + d]);
                const int cc = col0 + wn * 64 + nt * 8 + t * 2;
                float f0 = (c[mt][nt][0] * t0.y - c[mt][nt+4][0] * t0.x) * scl;
                float s0 = (c[mt][nt+4][0] * t0.y + c[mt][nt][0] * t0.x) * scl;
                float f1 = (c[mt][nt][1] * t0.w - c[mt][nt+4][1] * t0.z) * scl;
                float s1 = (c[mt][nt+4][1] * t0.w + c[mt][nt][1] * t0.z) * scl;
                *(__half2*)(dst + (size_t)r * 1024 + cc)      = __floats2half2_rn(f0, f1);
                *(__half2*)(dst + (size_t)r * 1024 + cc + 32) = __floats2half2_rn(s0, s1);
                f0 = (c[mt][nt][2] * t1.y - c[mt][nt+4][2] * t1.x) * scl;
                s0 = (c[mt][nt+4][2] * t1.y + c[mt][nt][2] * t1.x) * scl;
                f1 = (c[mt][nt][3] * t1.w - c[mt][nt+4][3] * t1.z) * scl;
                s1 = (c[mt][nt+4][3] * t1.w + c[mt][nt][3] * t1.z) * scl;
                *(__half2*)(dst + (size_t)(r + 8) * 1024 + cc)      = __floats2half2_rn(f0, f1);
                *(__half2*)(dst + (size_t)(r + 8) * 1024 + cc + 32) = __floats2half2_rn(s0, s1);
            }
        }
    }
}

// ---------------------------------------------------------------------------
// fp16-mma flash attention (unchanged from R13): cp.async K/V, ldmatrix frags.
// ---------------------------------------------------------------------------
#define BQ 128
#define QSTR 36
#define PSTR2 36
#define QBYTES (128 * QSTR * 4)
#define KVSTRB 144
#define KVB (64 * KVSTRB)
#define PBYTES (8 * 16 * PSTR2 * 4)
#define FH_SMEM_BYTES (QBYTES + 4 * KVB + PBYTES)   // 73728

__global__ __launch_bounds__(256) void flash_h()
{
    extern __shared__ char smc[];
    const uint32_t sb = smem_u32(smc);
    uint32_t* Qs = (uint32_t*)smc;
    uint32_t* Pw = (uint32_t*)(smc + QBYTES + 4 * KVB);

    const int qt = (int)gridDim.x - 1 - (int)blockIdx.x;
    const int h  = blockIdx.y;
    const int b  = blockIdx.z;
    const int tid  = threadIdx.x;
    const int warp = tid >> 5;
    const int lane = tid & 31;
    const int g = lane >> 2;
    const int t = lane & 3;
    const int q0 = qt * BQ;
    const int wrow0 = warp * 16;
    uint32_t* Ps = Pw + warp * 16 * PSTR2;

    {
        const int qr = tid >> 1;
        const int hc = (tid & 1) * 16;
        const __half* qg = g_qh + (((size_t)(b * S_ + q0 + qr)) * H_ + h) * DH + hc * 2;
        uint4 u0 = *(const uint4*)(qg);
        uint4 u1 = *(const uint4*)(qg + 8);
        uint4 u2 = *(const uint4*)(qg + 16);
        uint4 u3 = *(const uint4*)(qg + 24);
        *(uint4*)&Qs[qr * QSTR + hc]      = u0;
        *(uint4*)&Qs[qr * QSTR + hc + 4]  = u1;
        *(uint4*)&Qs[qr * QSTR + hc + 8]  = u2;
        *(uint4*)&Qs[qr * QSTR + hc + 12] = u3;
    }

    const int srow = tid >> 2;
    const int scp  = tid & 3;

    const uint32_t koffs = (uint32_t)(((lane & 7) + ((lane & 16) ? 8 : 0)) * KVSTRB
                                      + ((lane & 8) ? 16 : 0));
    const uint32_t voffs = (uint32_t)(((lane & 7) + ((lane & 8) ? 8 : 0)) * KVSTRB
                                      + ((lane & 16) ? 16 : 0));

    float o[8][4];
    #pragma unroll
    for (int nt = 0; nt < 8; nt++)
        #pragma unroll
        for (int r = 0; r < 4; r++) o[nt][r] = 0.f;
    float m0r = -INFINITY, m1r = -INFINITY, l0 = 0.f, l1 = 0.f;

    const int nkt = 2 * qt + 2;

    {
        const size_t goff = (((size_t)(b * S_ + srow)) * H_ + h) * DH + scp * 16;
        const uint32_t kd = sb + QBYTES + (uint32_t)(srow * KVSTRB + scp * 32);
        const uint32_t vd = kd + KVB;
        CP16(kd,      g_kh + goff);
        CP16(kd + 16, g_kh + goff + 8);
        CP16(vd,      g_vh + goff);
        CP16(vd + 16, g_vh + goff + 8);
        CP_COMMIT();
    }

    for (int kt = 0; kt < nkt; kt++) {
        const int k0 = kt * 64;
        const int buf = kt & 1;
        const uint32_t kbase = sb + QBYTES + (uint32_t)(buf * 2 * KVB);
        const uint32_t vbase = kbase + KVB;

        CP_WAIT0();
        __syncthreads();

        if (kt + 1 < nkt) {
            const int kn = (kt + 1) * 64;
            const size_t goff = (((size_t)(b * S_ + kn + srow)) * H_ + h) * DH + scp * 16;
            const uint32_t kd = sb + QBYTES + (uint32_t)((buf ^ 1) * 2 * KVB
                                 + srow * KVSTRB + scp * 32);
            const uint32_t vd = kd + KVB;
            CP16(kd,      g_kh + goff);
            CP16(kd + 16, g_kh + goff + 8);
            CP16(vd,      g_vh + goff);
            CP16(vd + 16, g_vh + goff + 8);
            CP_COMMIT();
        }

        float s[8][4];
        #pragma unroll
        for (int nt = 0; nt < 8; nt++)
            #pragma unroll
            for (int r = 0; r < 4; r++) s[nt][r] = 0.f;

        #pragma unroll
        for (int ks = 0; ks < 4; ks++) {
            const int kb = ks * 8;
            uint32_t a0 = Qs[(wrow0 + g) * QSTR + kb + t];
            uint32_t a1 = Qs[(wrow0 + g + 8) * QSTR + kb + t];
            uint32_t a2 = Qs[(wrow0 + g) * QSTR + kb + t + 4];
            uint32_t a3 = Qs[(wrow0 + g + 8) * QSTR + kb + t + 4];
            #pragma unroll
            for (int ntp = 0; ntp < 4; ntp++) {
                uint32_t b00, b01, b10, b11;
                LDSM4(b00, b01, b10, b11,
                      kbase + koffs + (uint32_t)(ntp * 16 * KVSTRB + ks * 32));
                MMA_F16(s[2*ntp][0],   s[2*ntp][1],   s[2*ntp][2],   s[2*ntp][3],
                        a0, a1, a2, a3, b00, b01);
                MMA_F16(s[2*ntp+1][0], s[2*ntp+1][1], s[2*ntp+1][2], s[2*ntp+1][3],
                        a0, a1, a2, a3, b10, b11);
            }
        }

        if (kt >= 2 * qt) {
            const int row0 = q0 + wrow0 + g;
            #pragma unroll
            for (int nt = 0; nt < 8; nt++) {
                const int col = k0 + nt * 8 + 2 * t;
                if (col     > row0)     s[nt][0] = -INFINITY;
                if (col + 1 > row0)     s[nt][1] = -INFINITY;
                if (col     > row0 + 8) s[nt][2] = -INFINITY;
                if (col + 1 > row0 + 8) s[nt][3] = -INFINITY;
            }
        }

        float mx0 = -INFINITY, mx1 = -INFINITY;
        #pragma unroll
        for (int nt = 0; nt < 8; nt++) {
            mx0 = fmaxf(mx0, fmaxf(s[nt][0], s[nt][1]));
            mx1 = fmaxf(mx1, fmaxf(s[nt][2], s[nt][3]));
        }
        mx0 = fmaxf(mx0, __shfl_xor_sync(0xffffffffu, mx0, 1));
        mx0 = fmaxf(mx0, __shfl_xor_sync(0xffffffffu, mx0, 2));
        mx1 = fmaxf(mx1, __shfl_xor_sync(0xffffffffu, mx1, 1));
        mx1 = fmaxf(mx1, __shfl_xor_sync(0xffffffffu, mx1, 2));

        const float mn0 = fmaxf(m0r, mx0);
        const float mn1 = fmaxf(m1r, mx1);
        const float sc0 = __expf(m0r - mn0);
        const float sc1 = __expf(m1r - mn1);

        float ls0 = 0.f, ls1 = 0.f;
        #pragma unroll
        for (int nt = 0; nt < 8; nt++) {
            float p0 = __expf(s[nt][0] - mn0);
            float p1 = __expf(s[nt][1] - mn0);
            float p2 = __expf(s[nt][2] - mn1);
            float p3 = __expf(s[nt][3] - mn1);
            ls0 += p0 + p1;
            ls1 += p2 + p3;
            __half2 h01 = __floats2half2_rn(p0, p1);
            __half2 h23 = __floats2half2_rn(p2, p3);
            Ps[g * PSTR2 + nt * 4 + t]       = *(uint32_t*)&h01;
            Ps[(g + 8) * PSTR2 + nt * 4 + t] = *(uint32_t*)&h23;
        }
        ls0 += __shfl_xor_sync(0xffffffffu, ls0, 1);
        ls0 += __shfl_xor_sync(0xffffffffu, ls0, 2);
        ls1 += __shfl_xor_sync(0xffffffffu, ls1, 1);
        ls1 += __shfl_xor_sync(0xffffffffu, ls1, 2);
        l0 = l0 * sc0 + ls0;
        l1 = l1 * sc1 + ls1;
        #pragma unroll
        for (int nt = 0; nt < 8; nt++) {
            o[nt][0] *= sc0; o[nt][1] *= sc0;
            o[nt][2] *= sc1; o[nt][3] *= sc1;
        }
        m0r = mn0; m1r = mn1;

        __syncwarp();

        #pragma unroll
        for (int ks = 0; ks < 4; ks++) {
            const int kb = ks * 8;
            uint32_t a0 = Ps[g * PSTR2 + kb + t];
            uint32_t a1 = Ps[(g + 8) * PSTR2 + kb + t];
            uint32_t a2 = Ps[g * PSTR2 + kb + t + 4];
            uint32_t a3 = Ps[(g + 8) * PSTR2 + kb + t + 4];
            #pragma unroll
            for (int ntp = 0; ntp < 4; ntp++) {
                uint32_t b00, b01, b10, b11;
                LDSM4T(b00, b01, b10, b11,
                       vbase + voffs + (uint32_t)(ks * 16 * KVSTRB + ntp * 32));
                MMA_F16(o[2*ntp][0],   o[2*ntp][1],   o[2*ntp][2],   o[2*ntp][3],
                        a0, a1, a2, a3, b00, b01);
                MMA_F16(o[2*ntp+1][0], o[2*ntp+1][1], o[2*ntp+1][2], o[2*ntp+1][3],
                        a0, a1, a2, a3, b10, b11);
            }
        }
        __syncwarp();
    }

    const float i0 = 1.f / l0;
    const float i1 = 1.f / l1;
    __half* xg0 = g_xh + (((size_t)(b * S_ + q0 + wrow0 + g)) * H_ + h) * DH;
    __half* xg1 = xg0 + (size_t)8 * H_ * DH;
    #pragma unroll
    for (int nt = 0; nt < 8; nt++) {
        *(__half2*)(xg0 + nt * 8 + 2 * t) = __floats2half2_rn(o[nt][0] * i0, o[nt][1] * i0);
        *(__half2*)(xg1 + nt * 8 + 2 * t) = __floats2half2_rn(o[nt][2] * i1, o[nt][3] * i1);
    }
}

// ---------------------------------------------------------------------------
extern "C" void kernel_launch(void* const* d_in, const int* in_sizes, int n_in,
                              void* d_out, int out_size)
{
    (void)in_sizes; (void)n_in; (void)out_size;
    const float* inputs = (const float*)d_in[0];
    const float* w_q    = (const float*)d_in[1];
    const float* w_k    = (const float*)d_in[2];
    const float* w_v    = (const float*)d_in[3];
    const float* w_out  = (const float*)d_in[4];
    const int*   segpos = (const int*)d_in[5];
    float* out = (float*)d_out;

    __half *qh, *kh, *vh, *xh, *ah, *wth;
    cudaGetSymbolAddress((void**)&qh, g_qh);
    cudaGetSymbolAddress((void**)&kh, g_kh);
    cudaGetSymbolAddress((void**)&vh, g_vh);
    cudaGetSymbolAddress((void**)&xh, g_xh);
    cudaGetSymbolAddress((void**)&ah, g_ah);
    cudaGetSymbolAddress((void**)&wth, g_wth);

    build_tab<<<S_ * 32 / 256, 256>>>();
    to_half<<<B_ * S_ * D_ / (256 * 8), 256>>>(inputs, ah);
    transpose_half<<<dim3(32, 32, 4), dim3(32, 8)>>>(w_q, w_k, w_v, w_out, wth);

    cudaFuncSetAttribute(gemm_h, cudaFuncAttributeMaxDynamicSharedMemorySize, GSMEM_BYTES);
    gemm_h<<<dim3(24, 64), 256, GSMEM_BYTES>>>(ah, wth, nullptr, qh, kh, vh, segpos, 1);

    cudaFuncSetAttribute(flash_h, cudaFuncAttributeMaxDynamicSharedMemorySize, FH_SMEM_BYTES);
    flash_h<<<dim3(S_ / BQ, H_, B_), 256, FH_SMEM_BYTES>>>();

    gemm_h<<<dim3(8, 64), 256, GSMEM_BYTES>>>(xh, wth + (size_t)3 * 1024 * 1024,
                                              out, nullptr, nullptr, nullptr, nullptr, 0);
}

// round 16
// speedup vs baseline: 1.1736x; 1.0638x over previous
#include <cuda_runtime.h>
#include <cuda_fp16.h>
#include <math.h>
#include <stdint.h>

#define B_ 4
#define S_ 2048
#define D_ 1024
#define H_ 16
#define DH 64

__device__ __half g_qh[B_*S_*H_*DH];     // fp16 q (post-rope, scaled)
__device__ __half g_kh[B_*S_*H_*DH];     // fp16 k (post-rope)
__device__ __half g_vh[B_*S_*H_*DH];     // fp16 v
__device__ __half g_xh[B_*S_*H_*DH];     // flash out (A of out-proj)
__device__ __half g_ah[B_*S_*D_];        // fp16 inputs
__device__ __half g_wth[4*1024*1024];    // transposed fp16 weights
__device__ float2 g_tab[S_*32];          // rope (sin,cos) table

__device__ __forceinline__ uint32_t smem_u32(const void* p) {
    uint32_t a;
    asm("{ .reg .u64 t; cvta.to.shared.u64 t, %1; cvt.u32.u64 %0, t; }" : "=r"(a) : "l"(p));
    return a;
}

__device__ __forceinline__ uint32_t h2pack(float x, float y) {
    __half2 h = __floats2half2_rn(x, y);
    return *(uint32_t*)&h;
}

#define MMA_F16(c0,c1,c2,c3,a0,a1,a2,a3,b0,b1)                           \
    asm volatile(                                                        \
        "mma.sync.aligned.m16n8k16.row.col.f32.f16.f16.f32 "             \
        "{%0,%1,%2,%3}, {%4,%5,%6,%7}, {%8,%9}, {%0,%1,%2,%3};"          \
        : "+f"(c0), "+f"(c1), "+f"(c2), "+f"(c3)                         \
        : "r"(a0), "r"(a1), "r"(a2), "r"(a3), "r"(b0), "r"(b1))

#define LDSM4(r0,r1,r2,r3,a)                                             \
    asm volatile("ldmatrix.sync.aligned.m8n8.x4.shared.b16 "             \
        "{%0,%1,%2,%3}, [%4];"                                           \
        : "=r"(r0), "=r"(r1), "=r"(r2), "=r"(r3) : "r"(a))

#define LDSM4T(r0,r1,r2,r3,a)                                            \
    asm volatile("ldmatrix.sync.aligned.m8n8.x4.trans.shared.b16 "       \
        "{%0,%1,%2,%3}, [%4];"                                           \
        : "=r"(r0), "=r"(r1), "=r"(r2), "=r"(r3) : "r"(a))

#define CP16(dst, src) asm volatile("cp.async.cg.shared.global [%0], [%1], 16;" :: "r"(dst), "l"(src))
#define CP_COMMIT()    asm volatile("cp.async.commit_group;" ::: "memory")
#define CP_WAIT2()     asm volatile("cp.async.wait_group 2;" ::: "memory")
#define CP_WAIT0()     asm volatile("cp.async.wait_group 0;" ::: "memory")

// ---------------------------------------------------------------------------
__global__ __launch_bounds__(256) void build_tab()
{
    const int idx = blockIdx.x * 256 + threadIdx.x;
    const int s = idx >> 5;
    const int d = idx & 31;
    const float ang = (float)s * expf(-(float)d * 0.28782313662425574f);
    float sv, cv;
    sincosf(ang, &sv, &cv);
    g_tab[idx] = make_float2(sv, cv);
}

__global__ __launch_bounds__(256) void to_half(
    const float* __restrict__ src, __half* __restrict__ dst)
{
    const size_t i = (size_t)(blockIdx.x * blockDim.x + threadIdx.x) * 8;
    float4 v0 = *(const float4*)(src + i);
    float4 v1 = *(const float4*)(src + i + 4);
    __half2 h[4];
    h[0] = __floats2half2_rn(v0.x, v0.y);
    h[1] = __floats2half2_rn(v0.z, v0.w);
    h[2] = __floats2half2_rn(v1.x, v1.y);
    h[3] = __floats2half2_rn(v1.z, v1.w);
    *(uint4*)(dst + i) = *(uint4*)h;
}

__global__ __launch_bounds__(256) void transpose_half(
    const float* __restrict__ w0, const float* __restrict__ w1,
    const float* __restrict__ w2, const float* __restrict__ w3,
    __half* __restrict__ dst)
{
    __shared__ float tile[32][33];
    const int z = blockIdx.z;
    const float* src = (z == 0) ? w0 : (z == 1) ? w1 : (z == 2) ? w2 : w3;
    __half* out = dst + (size_t)z * 1024 * 1024;
    const int n0 = blockIdx.x * 32;
    const int k0 = blockIdx.y * 32;
    const int tx = threadIdx.x;
    const int ty = threadIdx.y;

    #pragma unroll
    for (int j = 0; j < 4; j++)
        tile[ty + j * 8][tx] = src[(size_t)(k0 + ty + j * 8) * 1024 + n0 + tx];
    __syncthreads();
    #pragma unroll
    for (int j = 0; j < 4; j++)
        out[(size_t)(n0 + ty + j * 8) * 1024 + k0 + tx] = __float2half(tile[tx][ty + j * 8]);
}

// ---------------------------------------------------------------------------
// fp16 mma GEMM (exact R13 scheduling): BK=32, 4-stage cp.async wait2,
// ldmatrix fragment loads, regs pinned to 128 via launch_bounds(256,2).
// ---------------------------------------------------------------------------
#define GSTR 20
#define STG_WORDS (128 * GSTR)
#define GSMEM_BYTES (8 * STG_WORDS * 4)        // 80 KB

__global__ __launch_bounds__(256, 2) void gemm_h(
    const __half* __restrict__ A, const __half* __restrict__ Bt,
    float* __restrict__ Cf, __half* __restrict__ qh, __half* __restrict__ kh,
    __half* __restrict__ vh, const int* __restrict__ segpos, int fused)
{
    extern __shared__ uint32_t smw[];
    const uint32_t sbase = smem_u32(smw);

    const int tid  = threadIdx.x;
    const int warp = tid >> 5;
    const int lane = tid & 31;
    const int g = lane >> 2;
    const int t = lane & 3;
    const int wm = warp >> 1;
    const int wn = warp & 1;

    const int m0 = blockIdx.y * 128;
    const int n0 = blockIdx.x * 128;
    const int sel  = n0 >> 10;
    const int col0 = n0 & 1023;

    const int lrow = tid >> 1;
    const int hh   = (tid & 1) * 16;
    const __half* ag = A  + (size_t)(m0 + lrow) * 1024 + hh;
    const __half* bg = Bt + (size_t)(n0 + lrow) * 1024 + hh;
    const uint32_t adst = sbase + (uint32_t)(lrow * 80 + hh * 2);
    const uint32_t bdst = adst + 4 * STG_WORDS * 4;

    uint32_t aoff[2], boff[4];
    #pragma unroll
    for (int mt = 0; mt < 2; mt++)
        aoff[mt] = (uint32_t)(((wm * 32 + mt * 16 + (lane & 15)) * 20
                               + ((lane & 16) ? 4 : 0)) * 4);
    #pragma unroll
    for (int j = 0; j < 4; j++)
        boff[j] = (uint32_t)(((wn * 64 + j * 16 + (lane & 7) + ((lane & 16) ? 8 : 0)) * 20
                              + ((lane & 8) ? 4 : 0)) * 4);

    float c[2][8][4];
    #pragma unroll
    for (int mt = 0; mt < 2; mt++)
        #pragma unroll
        for (int nt = 0; nt < 8; nt++)
            #pragma unroll
            for (int r = 0; r < 4; r++) c[mt][nt][r] = 0.f;

    #pragma unroll
    for (int s = 0; s < 3; s++) {
        CP16(adst + s * 10240,      ag + s * 32);
        CP16(adst + s * 10240 + 16, ag + s * 32 + 8);
        CP16(bdst + s * 10240,      bg + s * 32);
        CP16(bdst + s * 10240 + 16, bg + s * 32 + 8);
        CP_COMMIT();
    }

    for (int kt = 0; kt < 32; kt++) {
        CP_WAIT2();
        __syncthreads();

        if (kt + 3 < 32) {
            const int s = (kt + 3) & 3;
            CP16(adst + s * 10240,      ag + (kt + 3) * 32);
            CP16(adst + s * 10240 + 16, ag + (kt + 3) * 32 + 8);
            CP16(bdst + s * 10240,      bg + (kt + 3) * 32);
            CP16(bdst + s * 10240 + 16, bg + (kt + 3) * 32 + 8);
        }
        CP_COMMIT();

        const int buf = kt & 3;
        const uint32_t abuf = sbase + (uint32_t)(buf * 10240);
        const uint32_t bbuf = abuf + 4 * STG_WORDS * 4;

        #pragma unroll
        for (int ks = 0; ks < 2; ks++) {
            const uint32_t kbyte = ks * 32;
            uint32_t afr[2][4];
            #pragma unroll
            for (int mt = 0; mt < 2; mt++)
                LDSM4(afr[mt][0], afr[mt][1], afr[mt][2], afr[mt][3],
                      abuf + aoff[mt] + kbyte);
            uint32_t bfr[8][2];
            #pragma unroll
            for (int j = 0; j < 4; j++)
                LDSM4(bfr[2*j][0], bfr[2*j][1], bfr[2*j+1][0], bfr[2*j+1][1],
                      bbuf + boff[j] + kbyte);
            #pragma unroll
            for (int mt = 0; mt < 2; mt++)
                #pragma unroll
                for (int nt = 0; nt < 8; nt++)
                    MMA_F16(c[mt][nt][0], c[mt][nt][1], c[mt][nt][2], c[mt][nt][3],
                            afr[mt][0], afr[mt][1], afr[mt][2], afr[mt][3],
                            bfr[nt][0], bfr[nt][1]);
        }
    }

    if (!fused) {
        #pragma unroll
        for (int mt = 0; mt < 2; mt++) {
            const int r = m0 + wm * 32 + mt * 16 + g;
            #pragma unroll
            for (int nt = 0; nt < 8; nt++) {
                const int cc = col0 + wn * 64 + nt * 8 + t * 2;
                *(float2*)(Cf + (size_t)r * 1024 + cc)       = make_float2(c[mt][nt][0], c[mt][nt][1]);
                *(float2*)(Cf + (size_t)(r + 8) * 1024 + cc) = make_float2(c[mt][nt][2], c[mt][nt][3]);
            }
        }
    } else if (sel == 2) {
        #pragma unroll
        for (int mt = 0; mt < 2; mt++) {
            const int r = m0 + wm * 32 + mt * 16 + g;
            #pragma unroll
            for (int nt = 0; nt < 8; nt++) {
                const int cc = col0 + wn * 64 + nt * 8 + t * 2;
                *(__half2*)(vh + (size_t)r * 1024 + cc) =
                    __floats2half2_rn(c[mt][nt][0], c[mt][nt][1]);
                *(__half2*)(vh + (size_t)(r + 8) * 1024 + cc) =
                    __floats2half2_rn(c[mt][nt][2], c[mt][nt][3]);
            }
        }
    } else {
        __half* dst = (sel == 0) ? qh : kh;
        const float scl = (sel == 0) ? 0.125f : 1.0f;
        #pragma unroll
        for (int mt = 0; mt < 2; mt++) {
            const int r = m0 + wm * 32 + mt * 16 + g;
            const int p0 = segpos[r];
            const int p1 = segpos[r + 8];
            #pragma unroll
            for (int nt = 0; nt < 4; nt++) {
                const int d = nt * 8 + t * 2;
                float4 t0 = *(const float4*)(&g_tab[p0 * 32 + d]);
                float4 t1 = *(const float4*)(&g_tab[p1 * 32 + d]);
                const int cc = col0 + wn * 64 + nt * 8 + t * 2;
                float f0 = (c[mt][nt][0] * t0.y - c[mt][nt+4][0] * t0.x) * scl;
                float s0 = (c[mt][nt+4][0] * t0.y + c[mt][nt][0] * t0.x) * scl;
                float f1 = (c[mt][nt][1] * t0.w - c[mt][nt+4][1] * t0.z) * scl;
                float s1 = (c[mt][nt+4][1] * t0.w + c[mt][nt][1] * t0.z) * scl;
                *(__half2*)(dst + (size_t)r * 1024 + cc)      = __floats2half2_rn(f0, f1);
                *(__half2*)(dst + (size_t)r * 1024 + cc + 32) = __floats2half2_rn(s0, s1);
                f0 = (c[mt][nt][2] * t1.y - c[mt][nt+4][2] * t1.x) * scl;
                s0 = (c[mt][nt+4][2] * t1.y + c[mt][nt][2] * t1.x) * scl;
                f1 = (c[mt][nt][3] * t1.w - c[mt][nt+4][3] * t1.z) * scl;
                s1 = (c[mt][nt+4][3] * t1.w + c[mt][nt][3] * t1.z) * scl;
                *(__half2*)(dst + (size_t)(r + 8) * 1024 + cc)      = __floats2half2_rn(f0, f1);
                *(__half2*)(dst + (size_t)(r + 8) * 1024 + cc + 32) = __floats2half2_rn(s0, s1);
            }
        }
    }
}

// ---------------------------------------------------------------------------
// fp16-mma flash attention: cp.async K/V (double buffer), ldmatrix B-frags,
// register-resident P (accumulator layout == A-fragment layout, no smem).
// ---------------------------------------------------------------------------
#define BQ 128
#define QSTR 36
#define QBYTES (128 * QSTR * 4)        // 18432
#define KVSTRB 144
#define KVB (64 * KVSTRB)              // 9216
#define FH_SMEM_BYTES (QBYTES + 4 * KVB)   // 55296

__global__ __launch_bounds__(256) void flash_h()
{
    extern __shared__ char smc[];
    const uint32_t sb = smem_u32(smc);
    uint32_t* Qs = (uint32_t*)smc;

    const int qt = (int)gridDim.x - 1 - (int)blockIdx.x;
    const int h  = blockIdx.y;
    const int b  = blockIdx.z;
    const int tid  = threadIdx.x;
    const int warp = tid >> 5;
    const int lane = tid & 31;
    const int g = lane >> 2;
    const int t = lane & 3;
    const int q0 = qt * BQ;
    const int wrow0 = warp * 16;

    // stage Q
    {
        const int qr = tid >> 1;
        const int hc = (tid & 1) * 16;
        const __half* qg = g_qh + (((size_t)(b * S_ + q0 + qr)) * H_ + h) * DH + hc * 2;
        uint4 u0 = *(const uint4*)(qg);
        uint4 u1 = *(const uint4*)(qg + 8);
        uint4 u2 = *(const uint4*)(qg + 16);
        uint4 u3 = *(const uint4*)(qg + 24);
        *(uint4*)&Qs[qr * QSTR + hc]      = u0;
        *(uint4*)&Qs[qr * QSTR + hc + 4]  = u1;
        *(uint4*)&Qs[qr * QSTR + hc + 8]  = u2;
        *(uint4*)&Qs[qr * QSTR + hc + 12] = u3;
    }

    const int srow = tid >> 2;
    const int scp  = tid & 3;

    const uint32_t koffs = (uint32_t)(((lane & 7) + ((lane & 16) ? 8 : 0)) * KVSTRB
                                      + ((lane & 8) ? 16 : 0));
    const uint32_t voffs = (uint32_t)(((lane & 7) + ((lane & 8) ? 8 : 0)) * KVSTRB
                                      + ((lane & 16) ? 16 : 0));

    float o[8][4];
    #pragma unroll
    for (int nt = 0; nt < 8; nt++)
        #pragma unroll
        for (int r = 0; r < 4; r++) o[nt][r] = 0.f;
    float m0r = -INFINITY, m1r = -INFINITY, l0 = 0.f, l1 = 0.f;

    const int nkt = 2 * qt + 2;

    // prologue: stage tile 0 into buffer 0
    {
        const size_t goff = (((size_t)(b * S_ + srow)) * H_ + h) * DH + scp * 16;
        const uint32_t kd = sb + QBYTES + (uint32_t)(srow * KVSTRB + scp * 32);
        const uint32_t vd = kd + KVB;
        CP16(kd,      g_kh + goff);
        CP16(kd + 16, g_kh + goff + 8);
        CP16(vd,      g_vh + goff);
        CP16(vd + 16, g_vh + goff + 8);
        CP_COMMIT();
    }

    for (int kt = 0; kt < nkt; kt++) {
        const int k0 = kt * 64;
        const int buf = kt & 1;
        const uint32_t kbase = sb + QBYTES + (uint32_t)(buf * 2 * KVB);
        const uint32_t vbase = kbase + KVB;

        CP_WAIT0();
        __syncthreads();

        if (kt + 1 < nkt) {
            const int kn = (kt + 1) * 64;
            const size_t goff = (((size_t)(b * S_ + kn + srow)) * H_ + h) * DH + scp * 16;
            const uint32_t kd = sb + QBYTES + (uint32_t)((buf ^ 1) * 2 * KVB
                                 + srow * KVSTRB + scp * 32);
            const uint32_t vd = kd + KVB;
            CP16(kd,      g_kh + goff);
            CP16(kd + 16, g_kh + goff + 8);
            CP16(vd,      g_vh + goff);
            CP16(vd + 16, g_vh + goff + 8);
            CP_COMMIT();
        }

        // S = Q @ K^T
        float s[8][4];
        #pragma unroll
        for (int nt = 0; nt < 8; nt++)
            #pragma unroll
            for (int r = 0; r < 4; r++) s[nt][r] = 0.f;

        #pragma unroll
        for (int ks = 0; ks < 4; ks++) {
            const int kb = ks * 8;
            uint32_t a0 = Qs[(wrow0 + g) * QSTR + kb + t];
            uint32_t a1 = Qs[(wrow0 + g + 8) * QSTR + kb + t];
            uint32_t a2 = Qs[(wrow0 + g) * QSTR + kb + t + 4];
            uint32_t a3 = Qs[(wrow0 + g + 8) * QSTR + kb + t + 4];
            #pragma unroll
            for (int ntp = 0; ntp < 4; ntp++) {
                uint32_t b00, b01, b10, b11;
                LDSM4(b00, b01, b10, b11,
                      kbase + koffs + (uint32_t)(ntp * 16 * KVSTRB + ks * 32));
                MMA_F16(s[2*ntp][0],   s[2*ntp][1],   s[2*ntp][2],   s[2*ntp][3],
                        a0, a1, a2, a3, b00, b01);
                MMA_F16(s[2*ntp+1][0], s[2*ntp+1][1], s[2*ntp+1][2], s[2*ntp+1][3],
                        a0, a1, a2, a3, b10, b11);
            }
        }

        if (kt >= 2 * qt) {
            const int row0 = q0 + wrow0 + g;
            #pragma unroll
            for (int nt = 0; nt < 8; nt++) {
                const int col = k0 + nt * 8 + 2 * t;
                if (col     > row0)     s[nt][0] = -INFINITY;
                if (col + 1 > row0)     s[nt][1] = -INFINITY;
                if (col     > row0 + 8) s[nt][2] = -INFINITY;
                if (col + 1 > row0 + 8) s[nt][3] = -INFINITY;
            }
        }

        // online softmax
        float mx0 = -INFINITY, mx1 = -INFINITY;
        #pragma unroll
        for (int nt = 0; nt < 8; nt++) {
            mx0 = fmaxf(mx0, fmaxf(s[nt][0], s[nt][1]));
            mx1 = fmaxf(mx1, fmaxf(s[nt][2], s[nt][3]));
        }
        mx0 = fmaxf(mx0, __shfl_xor_sync(0xffffffffu, mx0, 1));
        mx0 = fmaxf(mx0, __shfl_xor_sync(0xffffffffu, mx0, 2));
        mx1 = fmaxf(mx1, __shfl_xor_sync(0xffffffffu, mx1, 1));
        mx1 = fmaxf(mx1, __shfl_xor_sync(0xffffffffu, mx1, 2));

        const float mn0 = fmaxf(m0r, mx0);
        const float mn1 = fmaxf(m1r, mx1);
        const float sc0 = __expf(m0r - mn0);
        const float sc1 = __expf(m1r - mn1);

        float ls0 = 0.f, ls1 = 0.f;
        #pragma unroll
        for (int nt = 0; nt < 8; nt++) {
            s[nt][0] = __expf(s[nt][0] - mn0);
            s[nt][1] = __expf(s[nt][1] - mn0);
            s[nt][2] = __expf(s[nt][2] - mn1);
            s[nt][3] = __expf(s[nt][3] - mn1);
            ls0 += s[nt][0] + s[nt][1];
            ls1 += s[nt][2] + s[nt][3];
        }
        ls0 += __shfl_xor_sync(0xffffffffu, ls0, 1);
        ls0 += __shfl_xor_sync(0xffffffffu, ls0, 2);
        ls1 += __shfl_xor_sync(0xffffffffu, ls1, 1);
        ls1 += __shfl_xor_sync(0xffffffffu, ls1, 2);
        l0 = l0 * sc0 + ls0;
        l1 = l1 * sc1 + ls1;
        #pragma unroll
        for (int nt = 0; nt < 8; nt++) {
            o[nt][0] *= sc0; o[nt][1] *= sc0;
            o[nt][2] *= sc1; o[nt][3] *= sc1;
        }
        m0r = mn0; m1r = mn1;

        // O += P @ V — P taken straight from the s accumulators:
        // A-frag for kv-block ks (k=16): a0=(row g, k 2t,2t+1) = s[2ks][0..1],
        // a1=(row g+8) = s[2ks][2..3], a2/a3 = same at k+8 = s[2ks+1].
        #pragma unroll
        for (int ks = 0; ks < 4; ks++) {
            uint32_t a0 = h2pack(s[2*ks][0],   s[2*ks][1]);
            uint32_t a1 = h2pack(s[2*ks][2],   s[2*ks][3]);
            uint32_t a2 = h2pack(s[2*ks+1][0], s[2*ks+1][1]);
            uint32_t a3 = h2pack(s[2*ks+1][2], s[2*ks+1][3]);
            #pragma unroll
            for (int ntp = 0; ntp < 4; ntp++) {
                uint32_t b00, b01, b10, b11;
                LDSM4T(b00, b01, b10, b11,
                       vbase + voffs + (uint32_t)(ks * 16 * KVSTRB + ntp * 32));
                MMA_F16(o[2*ntp][0],   o[2*ntp][1],   o[2*ntp][2],   o[2*ntp][3],
                        a0, a1, a2, a3, b00, b01);
                MMA_F16(o[2*ntp+1][0], o[2*ntp+1][1], o[2*ntp+1][2], o[2*ntp+1][3],
                        a0, a1, a2, a3, b10, b11);
            }
        }
    }

    const float i0 = 1.f / l0;
    const float i1 = 1.f / l1;
    __half* xg0 = g_xh + (((size_t)(b * S_ + q0 + wrow0 + g)) * H_ + h) * DH;
    __half* xg1 = xg0 + (size_t)8 * H_ * DH;
    #pragma unroll
    for (int nt = 0; nt < 8; nt++) {
        *(__half2*)(xg0 + nt * 8 + 2 * t) = __floats2half2_rn(o[nt][0] * i0, o[nt][1] * i0);
        *(__half2*)(xg1 + nt * 8 + 2 * t) = __floats2half2_rn(o[nt][2] * i1, o[nt][3] * i1);
    }
}

// ---------------------------------------------------------------------------
extern "C" void kernel_launch(void* const* d_in, const int* in_sizes, int n_in,
                              void* d_out, int out_size)
{
    (void)in_sizes; (void)n_in; (void)out_size;
    const float* inputs = (const float*)d_in[0];
    const float* w_q    = (const float*)d_in[1];
    const float* w_k    = (const float*)d_in[2];
    const float* w_v    = (const float*)d_in[3];
    const float* w_out  = (const float*)d_in[4];
    const int*   segpos = (const int*)d_in[5];
    float* out = (float*)d_out;

    __half *qh, *kh, *vh, *xh, *ah, *wth;
    cudaGetSymbolAddress((void**)&qh, g_qh);
    cudaGetSymbolAddress((void**)&kh, g_kh);
    cudaGetSymbolAddress((void**)&vh, g_vh);
    cudaGetSymbolAddress((void**)&xh, g_xh);
    cudaGetSymbolAddress((void**)&ah, g_ah);
    cudaGetSymbolAddress((void**)&wth, g_wth);

    build_tab<<<S_ * 32 / 256, 256>>>();
    to_half<<<B_ * S_ * D_ / (256 * 8), 256>>>(inputs, ah);
    transpose_half<<<dim3(32, 32, 4), dim3(32, 8)>>>(w_q, w_k, w_v, w_out, wth);

    cudaFuncSetAttribute(gemm_h, cudaFuncAttributeMaxDynamicSharedMemorySize, GSMEM_BYTES);
    gemm_h<<<dim3(24, 64), 256, GSMEM_BYTES>>>(ah, wth, nullptr, qh, kh, vh, segpos, 1);

    cudaFuncSetAttribute(flash_h, cudaFuncAttributeMaxDynamicSharedMemorySize, FH_SMEM_BYTES);
    flash_h<<<dim3(S_ / BQ, H_, B_), 256, FH_SMEM_BYTES>>>();

    gemm_h<<<dim3(8, 64), 256, GSMEM_BYTES>>>(xh, wth + (size_t)3 * 1024 * 1024,
                                              out, nullptr, nullptr, nullptr, nullptr, 0);
}